// round 3
// baseline (speedup 1.0000x reference)
#include <cuda_runtime.h>
#include <math.h>

// ---------------- problem constants ----------------
#define BB_   8
#define NTOK  196
#define DD    768
#define NH    12
#define HD    64
#define MHOP  3072
#define BN    (BB_*NTOK)          // 1568
#define NELEM (BN*DD)             // 1204224
#define BETA  0.125f              // 1/sqrt(64)
#define INVB  8.0f

// ---------------- scratch (no cudaMalloc allowed) ----------------
__device__ __align__(256) float d_g [4L*BN*DD];
__device__ __align__(256) float d_K [4L*BN*DD];
__device__ __align__(256) float d_Q [4L*BN*DD];
__device__ __align__(256) float d_h [(long)BN*MHOP];
__device__ __align__(256) float d_dK[BN*DD];
__device__ __align__(256) float d_dQ[BN*DD];
__device__ __align__(256) float d_dg[BN*DD];
__device__ __align__(256) float d_gr[BN*DD];
__device__ float  d_mean[BN];
__device__ float  d_rstd[BN];
__device__ double d_eref;
__device__ double d_ecand[4];
__device__ float  d_chosen;
__constant__ float c_lrs[4] = {1.0f, 0.5f, 0.25f, 0.125f};

// ---------------- tiny kernels ----------------
__global__ void zero_kernel() {
    if (threadIdx.x == 0) d_eref = 0.0;
    if (threadIdx.x < 4)  d_ecand[threadIdx.x] = 0.0;
}

__global__ void select_kernel() {
    if (threadIdx.x == 0) {
        double eref = d_eref;
        float chosen = 0.0625f;
        if (d_ecand[3] < eref) chosen = 0.125f;
        if (d_ecand[2] < eref) chosen = 0.25f;
        if (d_ecand[1] < eref) chosen = 0.5f;
        if (d_ecand[0] < eref) chosen = 1.0f;
        d_chosen = chosen;
    }
}

__global__ void update_kernel(const float* __restrict__ x,
                              const float* __restrict__ grad,
                              float* __restrict__ out) {
    int i = blockIdx.x * 256 + threadIdx.x;
    if (i < NELEM) out[i] = x[i] - d_chosen * grad[i];
}

// ---------------- LayerNorm forward (optionally fused candidate build) ----------------
// grid.x = token, grid.z = candidate (1 for main). 256 threads, 3 elems/thread.
__global__ void ln_fwd_kernel(const float* __restrict__ x,
                              const float* __restrict__ grad,   // null for main
                              float* __restrict__ gout,
                              const float* __restrict__ gamma,
                              const float* __restrict__ delta,
                              float* meanOut, float* rstdOut, int useLr) {
    int t = blockIdx.x, z = blockIdx.z, tid = threadIdx.x;
    const float lr = useLr ? c_lrs[z] : 0.f;
    const float* xr = x + (long)t * DD;
    float v[3]; float s = 0.f;
#pragma unroll
    for (int i = 0; i < 3; i++) {
        int c = tid + i * 256;
        float xv = xr[c];
        if (useLr) xv -= lr * grad[(long)t * DD + c];
        v[i] = xv; s += xv;
    }
    __shared__ float red[256];
    red[tid] = s; __syncthreads();
    for (int o = 128; o; o >>= 1) { if (tid < o) red[tid] += red[tid + o]; __syncthreads(); }
    float mu = red[0] * (1.f / DD);
    __syncthreads();
    float s2 = 0.f;
#pragma unroll
    for (int i = 0; i < 3; i++) { float dv = v[i] - mu; s2 += dv * dv; }
    red[tid] = s2; __syncthreads();
    for (int o = 128; o; o >>= 1) { if (tid < o) red[tid] += red[tid + o]; __syncthreads(); }
    float rs = rsqrtf(red[0] * (1.f / DD) + 1e-5f);
    float* orow = gout + (long)z * NELEM + (long)t * DD;
#pragma unroll
    for (int i = 0; i < 3; i++) {
        int c = tid + i * 256;
        orow[c] = gamma[c] * (v[i] - mu) * rs + delta[c];
    }
    if (!useLr && tid == 0) { meanOut[t] = mu; rstdOut[t] = rs; }
}

// ---------------- LayerNorm backward ----------------
__global__ void ln_bwd_kernel(const float* __restrict__ x,
                              const float* __restrict__ mean,
                              const float* __restrict__ rstd,
                              const float* __restrict__ gamma,
                              const float* __restrict__ dgv,
                              float* __restrict__ dx) {
    int t = blockIdx.x, tid = threadIdx.x;
    float mu = mean[t], rs = rstd[t];
    const float* xr = x + (long)t * DD;
    const float* dr = dgv + (long)t * DD;
    float xh[3], dxh[3]; float s1 = 0.f, s2 = 0.f;
#pragma unroll
    for (int i = 0; i < 3; i++) {
        int c = tid + i * 256;
        xh[i]  = (xr[c] - mu) * rs;
        dxh[i] = dr[c] * gamma[c];
        s1 += dxh[i]; s2 += dxh[i] * xh[i];
    }
    __shared__ float r1[256], r2[256];
    r1[tid] = s1; r2[tid] = s2; __syncthreads();
    for (int o = 128; o; o >>= 1) {
        if (tid < o) { r1[tid] += r1[tid + o]; r2[tid] += r2[tid + o]; }
        __syncthreads();
    }
    float m1 = r1[0] * (1.f / DD), m2 = r2[0] * (1.f / DD);
#pragma unroll
    for (int i = 0; i < 3; i++) {
        int c = tid + i * 256;
        dx[(long)t * DD + c] = rs * (dxh[i] - m1 - xh[i] * m2);
    }
}

// ---------------- SGEMM 128x128x8 (fp32), optional B^T, fused epilogues ----------------
// epi: 0 = store alpha*acc (+=C if accumC)
//      1 = store relu(acc) to C AND atomicAdd(-0.5*sum relu^2) to e_base[z?]
//      2 = energy only (no store)
__global__ void __launch_bounds__(256)
sgemm_kernel(const float* __restrict__ A, const float* __restrict__ B,
             float* __restrict__ C,
             int Mrows, int Ncols, int Kdim, int transB,
             float alpha, int accumC, int epi,
             double* e_base, int e_per_z,
             long strideAz, long strideCz) {
    const int tid = threadIdx.x;
    const int m0 = blockIdx.y * 128;
    const int n0 = blockIdx.x * 128;
    A += (long)blockIdx.z * strideAz;
    if (C) C += (long)blockIdx.z * strideCz;

    __shared__ float As[8][128];
    __shared__ float Bs[8][128];

    float acc[8][8];
#pragma unroll
    for (int i = 0; i < 8; i++)
#pragma unroll
        for (int j = 0; j < 8; j++) acc[i][j] = 0.f;

    const int ar = tid >> 1, ac = (tid & 1) * 4;
    const int tm = (tid >> 4) * 8, tn = (tid & 15) * 8;

    for (int k0 = 0; k0 < Kdim; k0 += 8) {
        float4 av = make_float4(0.f, 0.f, 0.f, 0.f);
        if (m0 + ar < Mrows)
            av = *(const float4*)(A + (long)(m0 + ar) * Kdim + k0 + ac);
        As[ac + 0][ar] = av.x; As[ac + 1][ar] = av.y;
        As[ac + 2][ar] = av.z; As[ac + 3][ar] = av.w;
        if (transB) {
            float4 bv = *(const float4*)(B + (long)(n0 + ar) * Kdim + k0 + ac);
            Bs[ac + 0][ar] = bv.x; Bs[ac + 1][ar] = bv.y;
            Bs[ac + 2][ar] = bv.z; Bs[ac + 3][ar] = bv.w;
        } else {
            int bk = tid >> 5, bn = (tid & 31) * 4;
            *(float4*)&Bs[bk][bn] =
                *(const float4*)(B + (long)(k0 + bk) * Ncols + n0 + bn);
        }
        __syncthreads();
#pragma unroll
        for (int k = 0; k < 8; k++) {
            float a[8], b[8];
#pragma unroll
            for (int i = 0; i < 8; i++) { a[i] = As[k][tm + i]; b[i] = Bs[k][tn + i]; }
#pragma unroll
            for (int i = 0; i < 8; i++)
#pragma unroll
                for (int j = 0; j < 8; j++) acc[i][j] = fmaf(a[i], b[j], acc[i][j]);
        }
        __syncthreads();
    }

    if (epi == 0) {
#pragma unroll
        for (int i = 0; i < 8; i++) {
            int m = m0 + tm + i;
            if (m >= Mrows) break;
            float* Cr = C + (long)m * Ncols + n0 + tn;
#pragma unroll
            for (int j = 0; j < 8; j++) {
                float c = alpha * acc[i][j];
                if (accumC) c += Cr[j];
                Cr[j] = c;
            }
        }
    } else {
        double le = 0.0;
#pragma unroll
        for (int i = 0; i < 8; i++) {
            int m = m0 + tm + i;
            if (m >= Mrows) break;
            float* Cr = (epi == 1) ? (C + (long)m * Ncols + n0 + tn) : nullptr;
#pragma unroll
            for (int j = 0; j < 8; j++) {
                float c = acc[i][j];
                float r = c > 0.f ? c : 0.f;
                le += (double)r * (double)r;
                if (epi == 1) Cr[j] = r;
            }
        }
        __shared__ double ered[256];
        ered[tid] = le; __syncthreads();
        for (int o = 128; o; o >>= 1) { if (tid < o) ered[tid] += ered[tid + o]; __syncthreads(); }
        if (tid == 0)
            atomicAdd(e_base + (e_per_z ? blockIdx.z : 0), -0.5 * ered[0]);
    }
}

// ---------------- attention: energy (+optional softmax grads) per (b,h) ----------------
// grid.x = B*H (96), grid.z = candidate. 256 threads = 8 warps.
// smem: K[196][65] + Q[196][65] + lse[196] + rowbuf[8][200]
#define ATT_SMEM ((196*65*2 + 196 + 8*200) * 4)

template <bool GRAD>
__global__ void __launch_bounds__(256)
att_kernel(const float* __restrict__ Kall, const float* __restrict__ Qall,
           float* __restrict__ dK, float* __restrict__ dQ,
           double* e_base, int e_per_z) {
    extern __shared__ float sm[];
    const int LD = 65;
    float* Ksh = sm;
    float* Qsh = Ksh + 196 * LD;
    float* lse = Qsh + 196 * LD;
    float* rowbuf = lse + 196;
    __shared__ double wsum[8];

    int bh = blockIdx.x; int b = bh / NH; int h = bh % NH;
    long base = (long)blockIdx.z * NELEM + (long)b * NTOK * DD + h * HD;
    const float* Kg = Kall + base;
    const float* Qg = Qall + base;
    int tid = threadIdx.x, w = tid >> 5, lane = tid & 31;

    for (int i = tid; i < 196 * 16; i += 256) {
        int r = i >> 4, c4 = (i & 15) << 2;
        float4 kv = *(const float4*)(Kg + (long)r * DD + c4);
        float4 qv = *(const float4*)(Qg + (long)r * DD + c4);
        Ksh[r * LD + c4 + 0] = kv.x; Ksh[r * LD + c4 + 1] = kv.y;
        Ksh[r * LD + c4 + 2] = kv.z; Ksh[r * LD + c4 + 3] = kv.w;
        Qsh[r * LD + c4 + 0] = qv.x; Qsh[r * LD + c4 + 1] = qv.y;
        Qsh[r * LD + c4 + 2] = qv.z; Qsh[r * LD + c4 + 3] = qv.w;
    }
    __syncthreads();

    double lsesum = 0.0;
    float* rb = rowbuf + w * 200;

    for (int q = w; q < 196; q += 8) {
        const float* Qr = Qsh + q * LD;
        float mx = -1e30f;
        for (int k = lane; k < 196; k += 32) {
            const float* Kr = Ksh + k * LD;
            float s = 0.f;
#pragma unroll
            for (int y = 0; y < 64; y++) s = fmaf(Kr[y], Qr[y], s);
            s *= BETA;
            rb[k] = s;
            mx = fmaxf(mx, s);
        }
#pragma unroll
        for (int o = 16; o; o >>= 1) mx = fmaxf(mx, __shfl_xor_sync(0xffffffffu, mx, o));
        float se = 0.f;
        for (int k = lane; k < 196; k += 32) {
            float e = expf(rb[k] - mx);
            se += e;
            if (GRAD) rb[k] = e;
        }
#pragma unroll
        for (int o = 16; o; o >>= 1) se += __shfl_xor_sync(0xffffffffu, se, o);
        float l = mx + logf(se);
        if (lane == 0) lsesum += (double)l;
        if (GRAD) {
            if (lane == 0) lse[q] = l;
            float inv = 1.f / se;
            for (int k = lane; k < 196; k += 32) rb[k] *= inv;
            __syncwarp();
            int y0 = lane, y1 = lane + 32;
            float a0 = 0.f, a1 = 0.f;
            for (int k = 0; k < 196; k++) {
                float p = rb[k];
                a0 = fmaf(p, Ksh[k * LD + y0], a0);
                a1 = fmaf(p, Ksh[k * LD + y1], a1);
            }
            long o = (long)(b * NTOK + q) * DD + h * HD;
            dQ[o + y0] = -a0; dQ[o + y1] = -a1;
            __syncwarp();
        }
    }

    if (lane == 0) wsum[w] = lsesum;
    __syncthreads();
    if (tid == 0) {
        double t = 0.0;
        for (int i = 0; i < 8; i++) t += wsum[i];
        atomicAdd(e_base + (e_per_z ? blockIdx.z : 0), -(double)INVB * t);
    }

    if (GRAD) {
        __syncthreads();   // lse[] complete
        for (int k = w; k < 196; k += 8) {
            const float* Kr = Ksh + k * LD;
            for (int q = lane; q < 196; q += 32) {
                const float* Qr = Qsh + q * LD;
                float s = 0.f;
#pragma unroll
                for (int y = 0; y < 64; y++) s = fmaf(Kr[y], Qr[y], s);
                rb[q] = expf(BETA * s - lse[q]);
            }
            __syncwarp();
            int y0 = lane, y1 = lane + 32;
            float a0 = 0.f, a1 = 0.f;
            for (int q = 0; q < 196; q++) {
                float p = rb[q];
                a0 = fmaf(p, Qsh[q * LD + y0], a0);
                a1 = fmaf(p, Qsh[q * LD + y1], a1);
            }
            long o = (long)(b * NTOK + k) * DD + h * HD;
            dK[o + y0] = -a0; dK[o + y1] = -a1;
            __syncwarp();
        }
    }
}

// ---------------- host driver (graph-capturable, no sync, no alloc) ----------------
extern "C" void kernel_launch(void* const* d_in, const int* in_sizes, int n_in,
                              void* d_out, int out_size) {
    const float* x     = (const float*)d_in[0];
    const float* gamma = (const float*)d_in[1];
    const float* delta = (const float*)d_in[2];
    const float* wk    = (const float*)d_in[3];
    const float* wq    = (const float*)d_in[4];
    const float* xi    = (const float*)d_in[5];
    float* out = (float*)d_out;

    float *g, *K, *Q, *h, *dK, *dQ, *dg, *gr, *mean, *rstd;
    double *eref, *ecand;
    cudaGetSymbolAddress((void**)&g,    d_g);
    cudaGetSymbolAddress((void**)&K,    d_K);
    cudaGetSymbolAddress((void**)&Q,    d_Q);
    cudaGetSymbolAddress((void**)&h,    d_h);
    cudaGetSymbolAddress((void**)&dK,   d_dK);
    cudaGetSymbolAddress((void**)&dQ,   d_dQ);
    cudaGetSymbolAddress((void**)&dg,   d_dg);
    cudaGetSymbolAddress((void**)&gr,   d_gr);
    cudaGetSymbolAddress((void**)&mean, d_mean);
    cudaGetSymbolAddress((void**)&rstd, d_rstd);
    cudaGetSymbolAddress((void**)&eref,  d_eref);
    cudaGetSymbolAddress((void**)&ecand, d_ecand);

    cudaFuncSetAttribute(att_kernel<true>,  cudaFuncAttributeMaxDynamicSharedMemorySize, ATT_SMEM);
    cudaFuncSetAttribute(att_kernel<false>, cudaFuncAttributeMaxDynamicSharedMemorySize, ATT_SMEM);

    const long sZ = (long)NELEM;      // per-candidate stride

    zero_kernel<<<1, 32>>>();

    // ---- main pass: forward + gradient at x0 ----
    ln_fwd_kernel<<<dim3(BN, 1, 1), 256>>>(x, nullptr, g, gamma, delta, mean, rstd, 0);

    dim3 gP(DD / 128, (BN + 127) / 128, 1);          // 6 x 13
    sgemm_kernel<<<gP, 256>>>(g, wk, K, BN, DD, DD, 1, 1.f, 0, 0, nullptr, 0, 0, 0);
    sgemm_kernel<<<gP, 256>>>(g, wq, Q, BN, DD, DD, 1, 1.f, 0, 0, nullptr, 0, 0, 0);

    att_kernel<true><<<dim3(BB_ * NH, 1, 1), 256, ATT_SMEM>>>(K, Q, dK, dQ, eref, 0);

    dim3 gH(MHOP / 128, (BN + 127) / 128, 1);        // 24 x 13
    sgemm_kernel<<<gH, 256>>>(g, xi, h, BN, MHOP, DD, 1, 1.f, 0, 1, eref, 0, 0, 0);

    // dg = dK@Wk + dQ@Wq - h@Xi
    sgemm_kernel<<<gP, 256>>>(dK, wk, dg, BN, DD, DD, 0,  1.f, 0, 0, nullptr, 0, 0, 0);
    sgemm_kernel<<<gP, 256>>>(dQ, wq, dg, BN, DD, DD, 0,  1.f, 1, 0, nullptr, 0, 0, 0);
    sgemm_kernel<<<gP, 256>>>(h,  xi, dg, BN, DD, MHOP, 0, -1.f, 1, 0, nullptr, 0, 0, 0);

    ln_bwd_kernel<<<BN, 256>>>(x, mean, rstd, gamma, dg, gr);

    // ---- Armijo: 4 candidates x - lr_k*grad, batched via grid.z ----
    ln_fwd_kernel<<<dim3(BN, 1, 4), 256>>>(x, gr, g, gamma, delta, nullptr, nullptr, 1);

    dim3 gPc(DD / 128, (BN + 127) / 128, 4);
    sgemm_kernel<<<gPc, 256>>>(g, wk, K, BN, DD, DD, 1, 1.f, 0, 0, nullptr, 0, sZ, sZ);
    sgemm_kernel<<<gPc, 256>>>(g, wq, Q, BN, DD, DD, 1, 1.f, 0, 0, nullptr, 0, sZ, sZ);

    att_kernel<false><<<dim3(BB_ * NH, 1, 4), 256, ATT_SMEM>>>(K, Q, nullptr, nullptr, ecand, 1);

    dim3 gHc(MHOP / 128, (BN + 127) / 128, 4);
    sgemm_kernel<<<gHc, 256>>>(g, xi, nullptr, BN, MHOP, DD, 1, 1.f, 0, 2, ecand, 1, sZ, 0);

    select_kernel<<<1, 1>>>();
    update_kernel<<<(NELEM + 255) / 256, 256>>>(x, gr, out);
}

// round 4
// speedup vs baseline: 1.5478x; 1.5478x over previous
#include <cuda_runtime.h>
#include <math.h>

// ---------------- problem constants ----------------
#define BB_   8
#define NTOK  196
#define DD    768
#define NH    12
#define HD    64
#define MHOP  3072
#define BN    (BB_*NTOK)          // 1568
#define NELEM (BN*DD)             // 1204224
#define BETA  0.125f              // 1/sqrt(64)
#define INVB  8.0f

// ---------------- scratch (no cudaMalloc allowed) ----------------
__device__ __align__(256) float d_g [4L*BN*DD];
__device__ __align__(256) float d_K [4L*BN*DD];
__device__ __align__(256) float d_Q [4L*BN*DD];
__device__ __align__(256) float d_h [(long)BN*MHOP];
__device__ __align__(256) float d_dK[BN*DD];
__device__ __align__(256) float d_dQ[BN*DD];
__device__ __align__(256) float d_dg[BN*DD];
__device__ __align__(256) float d_gr[BN*DD];
__device__ float  d_mean[BN];
__device__ float  d_rstd[BN];
__device__ double d_eref;
__device__ double d_ecand[4];
__device__ float  d_chosen;
__constant__ float c_lrs[4] = {1.0f, 0.5f, 0.25f, 0.125f};

// ---------------- tiny kernels ----------------
__global__ void zero_kernel() {
    if (threadIdx.x == 0) d_eref = 0.0;
    if (threadIdx.x < 4)  d_ecand[threadIdx.x] = 0.0;
}

__global__ void select_kernel() {
    if (threadIdx.x == 0) {
        double eref = d_eref;
        float chosen = 0.0625f;
        if (d_ecand[3] < eref) chosen = 0.125f;
        if (d_ecand[2] < eref) chosen = 0.25f;
        if (d_ecand[1] < eref) chosen = 0.5f;
        if (d_ecand[0] < eref) chosen = 1.0f;
        d_chosen = chosen;
    }
}

__global__ void update_kernel(const float* __restrict__ x,
                              const float* __restrict__ grad,
                              float* __restrict__ out) {
    int i = blockIdx.x * 256 + threadIdx.x;
    if (i < NELEM) out[i] = x[i] - d_chosen * grad[i];
}

// ---------------- LayerNorm forward (optionally fused candidate build) ----------------
__global__ void ln_fwd_kernel(const float* __restrict__ x,
                              const float* __restrict__ grad,   // null for main
                              float* __restrict__ gout,
                              const float* __restrict__ gamma,
                              const float* __restrict__ delta,
                              float* meanOut, float* rstdOut, int useLr) {
    int t = blockIdx.x, z = blockIdx.z, tid = threadIdx.x;
    const float lr = useLr ? c_lrs[z] : 0.f;
    const float* xr = x + (long)t * DD;
    float v[3]; float s = 0.f;
#pragma unroll
    for (int i = 0; i < 3; i++) {
        int c = tid + i * 256;
        float xv = xr[c];
        if (useLr) xv -= lr * grad[(long)t * DD + c];
        v[i] = xv; s += xv;
    }
    __shared__ float red[256];
    red[tid] = s; __syncthreads();
    for (int o = 128; o; o >>= 1) { if (tid < o) red[tid] += red[tid + o]; __syncthreads(); }
    float mu = red[0] * (1.f / DD);
    __syncthreads();
    float s2 = 0.f;
#pragma unroll
    for (int i = 0; i < 3; i++) { float dv = v[i] - mu; s2 += dv * dv; }
    red[tid] = s2; __syncthreads();
    for (int o = 128; o; o >>= 1) { if (tid < o) red[tid] += red[tid + o]; __syncthreads(); }
    float rs = rsqrtf(red[0] * (1.f / DD) + 1e-5f);
    float* orow = gout + (long)z * NELEM + (long)t * DD;
#pragma unroll
    for (int i = 0; i < 3; i++) {
        int c = tid + i * 256;
        orow[c] = gamma[c] * (v[i] - mu) * rs + delta[c];
    }
    if (!useLr && tid == 0) { meanOut[t] = mu; rstdOut[t] = rs; }
}

// ---------------- LayerNorm backward ----------------
__global__ void ln_bwd_kernel(const float* __restrict__ x,
                              const float* __restrict__ mean,
                              const float* __restrict__ rstd,
                              const float* __restrict__ gamma,
                              const float* __restrict__ dgv,
                              float* __restrict__ dx) {
    int t = blockIdx.x, tid = threadIdx.x;
    float mu = mean[t], rs = rstd[t];
    const float* xr = x + (long)t * DD;
    const float* dr = dgv + (long)t * DD;
    float xh[3], dxh[3]; float s1 = 0.f, s2 = 0.f;
#pragma unroll
    for (int i = 0; i < 3; i++) {
        int c = tid + i * 256;
        xh[i]  = (xr[c] - mu) * rs;
        dxh[i] = dr[c] * gamma[c];
        s1 += dxh[i]; s2 += dxh[i] * xh[i];
    }
    __shared__ float r1[256], r2[256];
    r1[tid] = s1; r2[tid] = s2; __syncthreads();
    for (int o = 128; o; o >>= 1) {
        if (tid < o) { r1[tid] += r1[tid + o]; r2[tid] += r2[tid + o]; }
        __syncthreads();
    }
    float m1 = r1[0] * (1.f / DD), m2 = r2[0] * (1.f / DD);
#pragma unroll
    for (int i = 0; i < 3; i++) {
        int c = tid + i * 256;
        dx[(long)t * DD + c] = rs * (dxh[i] - m1 - xh[i] * m2);
    }
}

// ---------------- tf32 tensor-core GEMM ----------------
// SPLIT=1: single tf32 pass (candidate energies). SPLIT=3: hi/lo split,
// 3 MMA products -> near-fp32 accuracy (main gradient path).
// TRANSB=1: B is [N,K] row-major (compute A*B^T). TRANSB=0: B is [K,N].
// epi: 0 = store alpha*acc (+=C if accumC)
//      1 = store relu(acc) to C AND accumulate -0.5*relu^2 into e_base
//      2 = energy only (no store)
__device__ __forceinline__ unsigned f2tf(float x) {
    unsigned u;
    asm("cvt.rna.tf32.f32 %0, %1;" : "=r"(u) : "f"(x));
    return u;
}

__device__ __forceinline__ void mma8(float* c, const unsigned* a, const unsigned* b) {
    asm volatile("mma.sync.aligned.m16n8k8.row.col.f32.tf32.tf32.f32 "
                 "{%0,%1,%2,%3}, {%4,%5,%6,%7}, {%8,%9}, {%0,%1,%2,%3};"
                 : "+f"(c[0]), "+f"(c[1]), "+f"(c[2]), "+f"(c[3])
                 : "r"(a[0]), "r"(a[1]), "r"(a[2]), "r"(a[3]),
                   "r"(b[0]), "r"(b[1]));
}

template <int SPLIT, int TRANSB>
__global__ void __launch_bounds__(256)
mma_gemm(const float* __restrict__ A, const float* __restrict__ B,
         float* __restrict__ C, int Mrows, int Ncols, int Kdim,
         float alpha, int accumC, int epi,
         double* e_base, int e_per_z, long strideAz, long strideCz) {
    constexpr int NS  = (SPLIT == 3) ? 2 : 1;
    constexpr int LDT = 20;           // padded stride -> conflict-free frag loads
    constexpr int TS  = 128 * LDT;    // u32 per tile
    extern __shared__ unsigned smemu[];
    unsigned* AsBase = smemu;                      // [2 buf][NS][128][LDT]
    unsigned* BsBase = smemu + 2 * NS * TS;        // same, B as [n][k]

    const int tid = threadIdx.x;
    const int m0 = blockIdx.y * 128, n0 = blockIdx.x * 128;
    A += (long)blockIdx.z * strideAz;
    if (C) C += (long)blockIdx.z * strideCz;

    const int wid = tid >> 5, lane = tid & 31;
    const int wm = (wid >> 2) * 64, wn = (wid & 3) * 32;
    const int gr = lane >> 2, tg = lane & 3;

    float acc[4][4][4];
#pragma unroll
    for (int i = 0; i < 4; i++)
#pragma unroll
        for (int j = 0; j < 4; j++)
#pragma unroll
            for (int t = 0; t < 4; t++) acc[i][j][t] = 0.f;

    float ra[2][4], rb[2][4];

    auto loadG = [&](int k0) {
#pragma unroll
        for (int it = 0; it < 2; it++) {
            int idx = tid + it * 256;
            int r = idx >> 2, c4 = (idx & 3) * 4;
            float4 v = make_float4(0.f, 0.f, 0.f, 0.f);
            if (m0 + r < Mrows)
                v = *(const float4*)(A + (long)(m0 + r) * Kdim + k0 + c4);
            ra[it][0] = v.x; ra[it][1] = v.y; ra[it][2] = v.z; ra[it][3] = v.w;
            float4 w;
            if (TRANSB) {
                w = *(const float4*)(B + (long)(n0 + r) * Kdim + k0 + c4);
            } else {
                int k = idx >> 5, nn4 = (idx & 31) * 4;
                w = *(const float4*)(B + (long)(k0 + k) * Ncols + n0 + nn4);
            }
            rb[it][0] = w.x; rb[it][1] = w.y; rb[it][2] = w.z; rb[it][3] = w.w;
        }
    };

    auto storeS = [&](int buf) {
#pragma unroll
        for (int it = 0; it < 2; it++) {
            int idx = tid + it * 256;
            int r = idx >> 2, c4 = (idx & 3) * 4;
#pragma unroll
            for (int j = 0; j < 4; j++) {
                float v = ra[it][j];
                unsigned hi = f2tf(v);
                AsBase[(buf * NS) * TS + r * LDT + c4 + j] = hi;
                if (NS == 2) {
                    unsigned lo = f2tf(v - __uint_as_float(hi));
                    AsBase[(buf * NS + 1) * TS + r * LDT + c4 + j] = lo;
                }
                float w = rb[it][j];
                unsigned bhi = f2tf(w);
                int bm, bk;
                if (TRANSB) { bm = r; bk = c4 + j; }
                else        { bm = (idx & 31) * 4 + j; bk = idx >> 5; }
                BsBase[(buf * NS) * TS + bm * LDT + bk] = bhi;
                if (NS == 2) {
                    unsigned blo = f2tf(w - __uint_as_float(bhi));
                    BsBase[(buf * NS + 1) * TS + bm * LDT + bk] = blo;
                }
            }
        }
    };

    auto compute = [&](int buf) {
#pragma unroll
        for (int kk = 0; kk < 16; kk += 8) {
            unsigned af[NS][4][4], bf[NS][4][2];
#pragma unroll
            for (int s = 0; s < NS; s++) {
                const unsigned* Ab = AsBase + (buf * NS + s) * TS;
                const unsigned* Bb = BsBase + (buf * NS + s) * TS;
#pragma unroll
                for (int i = 0; i < 4; i++) {
                    int base = (wm + i * 16 + gr) * LDT + kk + tg;
                    af[s][i][0] = Ab[base];
                    af[s][i][1] = Ab[base + 8 * LDT];
                    af[s][i][2] = Ab[base + 4];
                    af[s][i][3] = Ab[base + 8 * LDT + 4];
                }
#pragma unroll
                for (int j = 0; j < 4; j++) {
                    int base = (wn + j * 8 + gr) * LDT + kk + tg;
                    bf[s][j][0] = Bb[base];
                    bf[s][j][1] = Bb[base + 4];
                }
            }
#pragma unroll
            for (int i = 0; i < 4; i++)
#pragma unroll
                for (int j = 0; j < 4; j++) {
                    mma8(acc[i][j], af[0][i], bf[0][j]);
                    if (NS == 2) {
                        mma8(acc[i][j], af[0][i], bf[1][j]);
                        mma8(acc[i][j], af[1][i], bf[0][j]);
                    }
                }
        }
    };

    const int nK = Kdim / 16;
    loadG(0);
    storeS(0);
    __syncthreads();
    for (int kt = 0; kt < nK; kt++) {
        int buf = kt & 1;
        bool hasNext = (kt + 1 < nK);
        if (hasNext) loadG((kt + 1) * 16);
        compute(buf);
        if (hasNext) storeS(buf ^ 1);
        __syncthreads();
    }

    if (epi == 0) {
#pragma unroll
        for (int i = 0; i < 4; i++)
#pragma unroll
            for (int half = 0; half < 2; half++) {
                int row = m0 + wm + i * 16 + gr + half * 8;
                if (row >= Mrows) continue;
                float* Cr = C + (long)row * Ncols + n0 + wn;
#pragma unroll
                for (int j = 0; j < 4; j++) {
                    int col = j * 8 + tg * 2;
                    float c0 = alpha * acc[i][j][half * 2 + 0];
                    float c1 = alpha * acc[i][j][half * 2 + 1];
                    if (accumC) { c0 += Cr[col]; c1 += Cr[col + 1]; }
                    Cr[col] = c0; Cr[col + 1] = c1;
                }
            }
    } else {
        double le = 0.0;
#pragma unroll
        for (int i = 0; i < 4; i++)
#pragma unroll
            for (int half = 0; half < 2; half++) {
                int row = m0 + wm + i * 16 + gr + half * 8;
                if (row >= Mrows) continue;
                float* Cr = (epi == 1) ? (C + (long)row * Ncols + n0 + wn) : nullptr;
#pragma unroll
                for (int j = 0; j < 4; j++) {
                    int col = j * 8 + tg * 2;
                    float c0 = acc[i][j][half * 2 + 0];
                    float c1 = acc[i][j][half * 2 + 1];
                    float r0 = c0 > 0.f ? c0 : 0.f;
                    float r1 = c1 > 0.f ? c1 : 0.f;
                    le += (double)r0 * (double)r0 + (double)r1 * (double)r1;
                    if (epi == 1) { Cr[col] = r0; Cr[col + 1] = r1; }
                }
            }
        __shared__ double ered[256];
        ered[tid] = le; __syncthreads();
        for (int o = 128; o; o >>= 1) {
            if (tid < o) ered[tid] += ered[tid + o];
            __syncthreads();
        }
        if (tid == 0)
            atomicAdd(e_base + (e_per_z ? blockIdx.z : 0), -0.5 * ered[0]);
    }
}

// ---------------- attention: energy (+optional softmax grads) per (b,h) ----------------
#define ATT_SMEM ((196*65*2 + 196 + 8*200) * 4)

template <bool GRAD>
__global__ void __launch_bounds__(256)
att_kernel(const float* __restrict__ Kall, const float* __restrict__ Qall,
           float* __restrict__ dK, float* __restrict__ dQ,
           double* e_base, int e_per_z) {
    extern __shared__ float sm[];
    const int LD = 65;
    float* Ksh = sm;
    float* Qsh = Ksh + 196 * LD;
    float* lse = Qsh + 196 * LD;
    float* rowbuf = lse + 196;
    __shared__ double wsum[8];

    int bh = blockIdx.x; int b = bh / NH; int h = bh % NH;
    long base = (long)blockIdx.z * NELEM + (long)b * NTOK * DD + h * HD;
    const float* Kg = Kall + base;
    const float* Qg = Qall + base;
    int tid = threadIdx.x, w = tid >> 5, lane = tid & 31;

    for (int i = tid; i < 196 * 16; i += 256) {
        int r = i >> 4, c4 = (i & 15) << 2;
        float4 kv = *(const float4*)(Kg + (long)r * DD + c4);
        float4 qv = *(const float4*)(Qg + (long)r * DD + c4);
        Ksh[r * LD + c4 + 0] = kv.x; Ksh[r * LD + c4 + 1] = kv.y;
        Ksh[r * LD + c4 + 2] = kv.z; Ksh[r * LD + c4 + 3] = kv.w;
        Qsh[r * LD + c4 + 0] = qv.x; Qsh[r * LD + c4 + 1] = qv.y;
        Qsh[r * LD + c4 + 2] = qv.z; Qsh[r * LD + c4 + 3] = qv.w;
    }
    __syncthreads();

    double lsesum = 0.0;
    float* rb = rowbuf + w * 200;

    for (int q = w; q < 196; q += 8) {
        const float* Qr = Qsh + q * LD;
        float mx = -1e30f;
        for (int k = lane; k < 196; k += 32) {
            const float* Kr = Ksh + k * LD;
            float s = 0.f;
#pragma unroll
            for (int y = 0; y < 64; y++) s = fmaf(Kr[y], Qr[y], s);
            s *= BETA;
            rb[k] = s;
            mx = fmaxf(mx, s);
        }
#pragma unroll
        for (int o = 16; o; o >>= 1) mx = fmaxf(mx, __shfl_xor_sync(0xffffffffu, mx, o));
        float se = 0.f;
        for (int k = lane; k < 196; k += 32) {
            float e = expf(rb[k] - mx);
            se += e;
            if (GRAD) rb[k] = e;
        }
#pragma unroll
        for (int o = 16; o; o >>= 1) se += __shfl_xor_sync(0xffffffffu, se, o);
        float l = mx + logf(se);
        if (lane == 0) lsesum += (double)l;
        if (GRAD) {
            if (lane == 0) lse[q] = l;
            float inv = 1.f / se;
            for (int k = lane; k < 196; k += 32) rb[k] *= inv;
            __syncwarp();
            int y0 = lane, y1 = lane + 32;
            float a0 = 0.f, a1 = 0.f;
            for (int k = 0; k < 196; k++) {
                float p = rb[k];
                a0 = fmaf(p, Ksh[k * LD + y0], a0);
                a1 = fmaf(p, Ksh[k * LD + y1], a1);
            }
            long o = (long)(b * NTOK + q) * DD + h * HD;
            dQ[o + y0] = -a0; dQ[o + y1] = -a1;
            __syncwarp();
        }
    }

    if (lane == 0) wsum[w] = lsesum;
    __syncthreads();
    if (tid == 0) {
        double t = 0.0;
        for (int i = 0; i < 8; i++) t += wsum[i];
        atomicAdd(e_base + (e_per_z ? blockIdx.z : 0), -(double)INVB * t);
    }

    if (GRAD) {
        __syncthreads();   // lse[] complete
        for (int k = w; k < 196; k += 8) {
            const float* Kr = Ksh + k * LD;
            for (int q = lane; q < 196; q += 32) {
                const float* Qr = Qsh + q * LD;
                float s = 0.f;
#pragma unroll
                for (int y = 0; y < 64; y++) s = fmaf(Kr[y], Qr[y], s);
                rb[q] = expf(BETA * s - lse[q]);
            }
            __syncwarp();
            int y0 = lane, y1 = lane + 32;
            float a0 = 0.f, a1 = 0.f;
            for (int q = 0; q < 196; q++) {
                float p = rb[q];
                a0 = fmaf(p, Qsh[q * LD + y0], a0);
                a1 = fmaf(p, Qsh[q * LD + y1], a1);
            }
            long o = (long)(b * NTOK + k) * DD + h * HD;
            dK[o + y0] = -a0; dK[o + y1] = -a1;
            __syncwarp();
        }
    }
}

// ---------------- host driver (graph-capturable, no sync, no alloc) ----------------
extern "C" void kernel_launch(void* const* d_in, const int* in_sizes, int n_in,
                              void* d_out, int out_size) {
    const float* x     = (const float*)d_in[0];
    const float* gamma = (const float*)d_in[1];
    const float* delta = (const float*)d_in[2];
    const float* wk    = (const float*)d_in[3];
    const float* wq    = (const float*)d_in[4];
    const float* xi    = (const float*)d_in[5];
    float* out = (float*)d_out;

    float *g, *K, *Q, *h, *dK, *dQ, *dg, *gr, *mean, *rstd;
    double *eref, *ecand;
    cudaGetSymbolAddress((void**)&g,    d_g);
    cudaGetSymbolAddress((void**)&K,    d_K);
    cudaGetSymbolAddress((void**)&Q,    d_Q);
    cudaGetSymbolAddress((void**)&h,    d_h);
    cudaGetSymbolAddress((void**)&dK,   d_dK);
    cudaGetSymbolAddress((void**)&dQ,   d_dQ);
    cudaGetSymbolAddress((void**)&dg,   d_dg);
    cudaGetSymbolAddress((void**)&gr,   d_gr);
    cudaGetSymbolAddress((void**)&mean, d_mean);
    cudaGetSymbolAddress((void**)&rstd, d_rstd);
    cudaGetSymbolAddress((void**)&eref,  d_eref);
    cudaGetSymbolAddress((void**)&ecand, d_ecand);

    // dynamic smem sizes: 2 buf * NS splits * (A+B) * 128*20 u32
    const int SM3 = 2 * 2 * 2 * 128 * 20 * 4;   // 81920 B  (SPLIT=3)
    const int SM1 = 2 * 1 * 2 * 128 * 20 * 4;   // 40960 B  (SPLIT=1)

    cudaFuncSetAttribute(mma_gemm<3, 1>, cudaFuncAttributeMaxDynamicSharedMemorySize, SM3);
    cudaFuncSetAttribute(mma_gemm<3, 0>, cudaFuncAttributeMaxDynamicSharedMemorySize, SM3);
    cudaFuncSetAttribute(mma_gemm<1, 1>, cudaFuncAttributeMaxDynamicSharedMemorySize, SM1);
    cudaFuncSetAttribute(att_kernel<true>,  cudaFuncAttributeMaxDynamicSharedMemorySize, ATT_SMEM);
    cudaFuncSetAttribute(att_kernel<false>, cudaFuncAttributeMaxDynamicSharedMemorySize, ATT_SMEM);

    const long sZ = (long)NELEM;      // per-candidate stride

    zero_kernel<<<1, 32>>>();

    // ---- main pass: forward + gradient at x0 (split-tf32, near-fp32) ----
    ln_fwd_kernel<<<dim3(BN, 1, 1), 256>>>(x, nullptr, g, gamma, delta, mean, rstd, 0);

    dim3 gP(DD / 128, (BN + 127) / 128, 1);          // 6 x 13
    mma_gemm<3, 1><<<gP, 256, SM3>>>(g, wk, K, BN, DD, DD, 1.f, 0, 0, nullptr, 0, 0, 0);
    mma_gemm<3, 1><<<gP, 256, SM3>>>(g, wq, Q, BN, DD, DD, 1.f, 0, 0, nullptr, 0, 0, 0);

    att_kernel<true><<<dim3(BB_ * NH, 1, 1), 256, ATT_SMEM>>>(K, Q, dK, dQ, eref, 0);

    dim3 gH(MHOP / 128, (BN + 127) / 128, 1);        // 24 x 13
    mma_gemm<3, 1><<<gH, 256, SM3>>>(g, xi, h, BN, MHOP, DD, 1.f, 0, 1, eref, 0, 0, 0);

    // dg = dK@Wk + dQ@Wq - h@Xi
    mma_gemm<3, 0><<<gP, 256, SM3>>>(dK, wk, dg, BN, DD, DD,   1.f, 0, 0, nullptr, 0, 0, 0);
    mma_gemm<3, 0><<<gP, 256, SM3>>>(dQ, wq, dg, BN, DD, DD,   1.f, 1, 0, nullptr, 0, 0, 0);
    mma_gemm<3, 0><<<gP, 256, SM3>>>(h,  xi, dg, BN, DD, MHOP, -1.f, 1, 0, nullptr, 0, 0, 0);

    ln_bwd_kernel<<<BN, 256>>>(x, mean, rstd, gamma, dg, gr);

    // ---- Armijo: 4 candidates x - lr_k*grad, batched via grid.z (1-pass tf32) ----
    ln_fwd_kernel<<<dim3(BN, 1, 4), 256>>>(x, gr, g, gamma, delta, nullptr, nullptr, 1);

    dim3 gPc(DD / 128, (BN + 127) / 128, 4);
    mma_gemm<1, 1><<<gPc, 256, SM1>>>(g, wk, K, BN, DD, DD, 1.f, 0, 0, nullptr, 0, sZ, sZ);
    mma_gemm<1, 1><<<gPc, 256, SM1>>>(g, wq, Q, BN, DD, DD, 1.f, 0, 0, nullptr, 0, sZ, sZ);

    att_kernel<false><<<dim3(BB_ * NH, 1, 4), 256, ATT_SMEM>>>(K, Q, nullptr, nullptr, ecand, 1);

    dim3 gHc(MHOP / 128, (BN + 127) / 128, 4);
    mma_gemm<1, 1><<<gHc, 256, SM1>>>(g, xi, nullptr, BN, MHOP, DD, 1.f, 0, 2, ecand, 1, sZ, 0);

    select_kernel<<<1, 1>>>();
    update_kernel<<<(NELEM + 255) / 256, 256>>>(x, gr, out);
}